// round 3
// baseline (speedup 1.0000x reference)
#include <cuda_runtime.h>
#include <cstdint>

#define BB 16
#define HH 512
#define WW 512
#define HW (HH*WW)

// Scratch (no allocations allowed -> __device__ globals)
__device__ unsigned short g_cm  [BB*HW];      // packed (mask<<8)|colsum per pixel
__device__ float          g_part[BB*HH*4];    // per-(b,row) partial sums
__device__ float          g_lossb[BB];        // per-batch loss
__device__ unsigned int   g_count;            // completion counter (zero-init, self-reset)

// ---------------------------------------------------------------------------
// Pass 1: vertical sliding 31-sum of remapped mask, fused with u8 mask copy,
// packed as u16 = (mask<<8)|colsum. Ring buffer in smem -> each mask element
// is loaded from global exactly once per block (halo only between segments).
// Dtype (int64 vs int32) detected per-block from the first 64 odd 32-bit
// words (same 256B region for all blocks -> L2 broadcast).
// Grid: (B, 4 x-chunks, 8 y-segments of 64 rows), 128 threads (one column each).
__global__ void pass1_kernel(const int* __restrict__ mask32) {
    const int tid = threadIdx.x;
    const int b   = blockIdx.x;
    const int x   = blockIdx.y * 128 + tid;
    const int ystart = blockIdx.z * 64;
    const int yend   = ystart + 64;

    // --- dtype detection: int64 non-negative => all odd words are 0 ---
    __shared__ int sflag;
    if (tid == 0) sflag = 0;
    __syncthreads();
    {
        int v = mask32[2 * (tid & 63) + 1];
        if (v != 0) atomicOr(&sflag, 1);
    }
    __syncthreads();
    const int shift = sflag ? 0 : 1;   // 1 => int64 (stride-2 i32 words)

    const int* mb = mask32 + (((size_t)b * HW) << shift);
    unsigned short* cm = g_cm + (size_t)b * HW;

    __shared__ unsigned char ring[31][128];

    int sum = 0;
    // warm-up: rows [ystart-15, ystart+14]
    for (int yy = ystart - 15; yy < ystart + 15; ++yy) {
        if (yy >= 0) {
            int v = mb[(size_t)(yy * WW + x) << shift];
            unsigned char u = (unsigned char)((v == 255) ? 0 : v);
            sum += u;
            ring[((unsigned)yy) % 31u][tid] = u;
        }
    }
    #pragma unroll 4
    for (int y = ystart; y < yend; ++y) {
        int yin = y + 15;
        if (yin < HH) {
            int v = mb[(size_t)(yin * WW + x) << shift];
            unsigned char u = (unsigned char)((v == 255) ? 0 : v);
            sum += u;
            ring[((unsigned)yin) % 31u][tid] = u;
        }
        unsigned char mrow = ring[((unsigned)y) % 31u][tid];
        cm[y * WW + x] = (unsigned short)(((int)mrow << 8) | sum);
        int yout = y - 15;
        if (yout >= 0) sum -= (int)ring[((unsigned)yout) % 31u][tid];
    }
}

// ---------------------------------------------------------------------------
// Pass 2: per-row horizontal window via shared prefix scan, fused with
// log-softmax CE + weighted IoU terms; deterministic block reduction of the
// 4 accumulators into g_part[(b*H+y)*4 + k].
// Grid: (H, B), 512 threads (one pixel each).
__global__ void pass2_kernel(const float* __restrict__ pred) {
    const int y = blockIdx.x;
    const int b = blockIdx.y;
    const int x = threadIdx.x;
    const int lane = x & 31, warp = x >> 5;

    __shared__ float P[WW];
    __shared__ float wsum[16];
    __shared__ float red[16][4];

    const size_t rowbase = (size_t)b * HW + (size_t)y * WW;

    const unsigned short cmv = g_cm[rowbase + x];

    // inclusive prefix scan of colsum row (exact: integer-valued <= 15872)
    float v = (float)(cmv & 255u);
    #pragma unroll
    for (int o = 1; o < 32; o <<= 1) {
        float n = __shfl_up_sync(0xffffffffu, v, o);
        if (lane >= o) v += n;
    }
    if (lane == 31) wsum[warp] = v;
    __syncthreads();
    if (warp == 0) {
        float t = (lane < 16) ? wsum[lane] : 0.f;
        #pragma unroll
        for (int o = 1; o < 16; o <<= 1) {
            float n = __shfl_up_sync(0xffffffffu, t, o);
            if (lane >= o) t += n;
        }
        if (lane < 16) wsum[lane] = t;
    }
    __syncthreads();
    float pref = v + ((warp > 0) ? wsum[warp - 1] : 0.f);
    P[x] = pref;
    __syncthreads();

    const int hi = (x + 15 < WW - 1) ? (x + 15) : (WW - 1);
    float win = P[hi] - ((x >= 16) ? P[x - 16] : 0.f);
    float pooled = win * (1.0f / 961.0f);

    float mf = (float)(cmv >> 8);

    const float* pb = pred + ((size_t)b * 2) * HW + (size_t)y * WW + x;
    float p0 = pb[0];
    float p1 = pb[HW];

    float mx = fmaxf(p0, p1);
    float e0 = __expf(p0 - mx), e1 = __expf(p1 - mx);
    float lse = mx + __logf(e0 + e1);
    float logp0 = p0 - lse, logp1 = p1 - lse;

    float wbce = (mf > 0.5f) ? -logp1 : -logp0;
    float p1p  = __expf(logp1);
    float weit = 1.0f + 5.0f * fabsf(pooled - mf);

    float a0 = weit;                 // weit_sum
    float a1 = weit * wbce;          // weighted BCE
    float a2 = p1p * mf * weit;      // inter
    float a3 = (p1p + mf) * weit;    // cardinality

    // block reduce (deterministic)
    #pragma unroll
    for (int o = 16; o > 0; o >>= 1) {
        a0 += __shfl_down_sync(0xffffffffu, a0, o);
        a1 += __shfl_down_sync(0xffffffffu, a1, o);
        a2 += __shfl_down_sync(0xffffffffu, a2, o);
        a3 += __shfl_down_sync(0xffffffffu, a3, o);
    }
    if (lane == 0) { red[warp][0] = a0; red[warp][1] = a1; red[warp][2] = a2; red[warp][3] = a3; }
    __syncthreads();
    if (warp == 0) {
        float r0 = (lane < 16) ? red[lane][0] : 0.f;
        float r1 = (lane < 16) ? red[lane][1] : 0.f;
        float r2 = (lane < 16) ? red[lane][2] : 0.f;
        float r3 = (lane < 16) ? red[lane][3] : 0.f;
        #pragma unroll
        for (int o = 8; o > 0; o >>= 1) {
            r0 += __shfl_down_sync(0xffffffffu, r0, o);
            r1 += __shfl_down_sync(0xffffffffu, r1, o);
            r2 += __shfl_down_sync(0xffffffffu, r2, o);
            r3 += __shfl_down_sync(0xffffffffu, r3, o);
        }
        if (lane == 0) {
            float* out = g_part + ((size_t)b * HH + y) * 4;
            out[0] = r0; out[1] = r1; out[2] = r2; out[3] = r3;
        }
    }
}

// ---------------------------------------------------------------------------
// Pass 3: 16 blocks, block b reduces batch b's 512 row-partials (float4,
// coalesced), computes batch loss; last block (fenced atomic counter)
// averages the 16 losses, writes out[0], resets the counter (replay-safe).
__global__ void pass3_kernel(float* __restrict__ out) {
    const int b   = blockIdx.x;
    const int tid = threadIdx.x;          // 128 threads
    const int lane = tid & 31, warp = tid >> 5;

    const float4* p = (const float4*)g_part + (size_t)b * HH;
    float s0 = 0.f, s1 = 0.f, s2 = 0.f, s3 = 0.f;
    #pragma unroll
    for (int i = tid; i < HH; i += 128) {
        float4 v = p[i];
        s0 += v.x; s1 += v.y; s2 += v.z; s3 += v.w;
    }
    #pragma unroll
    for (int o = 16; o > 0; o >>= 1) {
        s0 += __shfl_down_sync(0xffffffffu, s0, o);
        s1 += __shfl_down_sync(0xffffffffu, s1, o);
        s2 += __shfl_down_sync(0xffffffffu, s2, o);
        s3 += __shfl_down_sync(0xffffffffu, s3, o);
    }
    __shared__ float red[4][4];
    if (lane == 0) { red[warp][0] = s0; red[warp][1] = s1; red[warp][2] = s2; red[warp][3] = s3; }
    __syncthreads();
    if (tid == 0) {
        float r0 = red[0][0] + red[1][0] + red[2][0] + red[3][0];
        float r1 = red[0][1] + red[1][1] + red[2][1] + red[3][1];
        float r2 = red[0][2] + red[1][2] + red[2][2] + red[3][2];
        float r3 = red[0][3] + red[1][3] + red[2][3] + red[3][3];

        float wbce  = r1 / r0;
        float inter = r2;
        float uni   = r3 - r2;                     // cardinality - inter
        float wiou  = 1.f - (inter + 1.f) / (uni + 1.f);
        g_lossb[b] = wbce + wiou;

        __threadfence();
        unsigned int old = atomicAdd(&g_count, 1u);
        if (old == (BB - 1)) {
            __threadfence();
            volatile float* lb = g_lossb;
            float t = 0.f;
            #pragma unroll
            for (int i = 0; i < BB; ++i) t += lb[i];
            out[0] = t * (1.f / (float)BB);
            atomicExch(&g_count, 0u);              // reset for next graph replay
        }
    }
}

// ---------------------------------------------------------------------------
extern "C" void kernel_launch(void* const* d_in, const int* in_sizes, int n_in,
                              void* d_out, int out_size) {
    const float* pred   = (const float*)d_in[0];
    const int*   mask32 = (const int*)d_in[1];   // 32-bit view; dtype detected in-kernel
    float* out = (float*)d_out;

    pass1_kernel<<<dim3(BB, 4, 8), 128>>>(mask32);
    pass2_kernel<<<dim3(HH, BB), 512>>>(pred);
    pass3_kernel<<<BB, 128>>>(out);
}

// round 4
// speedup vs baseline: 1.3220x; 1.3220x over previous
#include <cuda_runtime.h>
#include <cstdint>

#define BB 16
#define HH 512
#define WW 512
#define HW (HH*WW)
#define SEG 32            // output rows per pass1 block
#define TROWS (SEG + 30)  // 62 tile rows (15 halo each side)

// Scratch (no allocations allowed -> __device__ globals)
__device__ unsigned short g_cm  [BB*HW];      // packed (mask<<8)|colsum per pixel
__device__ float          g_part[BB*HH*4];    // per-(b,row) partial sums
__device__ float          g_lossb[BB];        // per-batch loss
__device__ unsigned int   g_count;            // completion counter (zero-init, self-reset)

// ---------------------------------------------------------------------------
// Pass 1 (v2): cooperative smem tile load (62 rows x 256 cols, fully
// independent coalesced loads for high MLP), then vertical sliding 31-sum
// from smem, packed as u16 = (mask<<8)|colsum.
// Dtype (int64 vs int32) detected per-block from the first 64 odd 32-bit
// words (same 256B region for all blocks -> L2 broadcast).
// Grid: (B, 2 x-chunks of 256, 16 y-segments of 32 rows), 256 threads.
__global__ void pass1_kernel(const int* __restrict__ mask32) {
    const int tid = threadIdx.x;                 // 0..255, column within chunk
    const int b   = blockIdx.x;
    const int cx  = blockIdx.y * 256;
    const int y0  = blockIdx.z * SEG;

    // --- dtype detection: int64 non-negative => all odd words are 0 ---
    __shared__ int sflag;
    if (tid == 0) sflag = 0;
    __syncthreads();
    {
        int v = mask32[2 * (tid & 63) + 1];
        if (v != 0) atomicOr(&sflag, 1);
    }
    __syncthreads();
    const int shift = sflag ? 0 : 1;             // 1 => int64 (stride-2 i32 words)

    const int* mb = mask32 + (((size_t)b * HW) << shift);

    __shared__ unsigned char tile[TROWS][256];

    // Cooperative tile load: row r holds global row y0-15+r (zeros outside).
    // Each iteration is an independent coalesced 256-thread row load.
    #pragma unroll 16
    for (int r = 0; r < TROWS; ++r) {
        const int y = y0 - 15 + r;
        unsigned char u = 0;
        if (y >= 0 && y < HH) {
            int v = mb[(size_t)(y * WW + cx + tid) << shift];
            u = (unsigned char)((v == 255) ? 0 : v);
        }
        tile[r][tid] = u;
    }
    __syncthreads();

    // Vertical sliding 31-sum from smem (same-word byte reads: conflict-free).
    int sum = 0;
    #pragma unroll
    for (int r = 0; r < 31; ++r) sum += (int)tile[r][tid];

    unsigned short* cm = g_cm + (size_t)b * HW;
    #pragma unroll
    for (int i = 0; i < SEG; ++i) {
        const int y = y0 + i;
        const int m = (int)tile[15 + i][tid];
        cm[y * WW + cx + tid] = (unsigned short)((m << 8) | sum);
        if (i < SEG - 1)
            sum += (int)tile[31 + i][tid] - (int)tile[i][tid];
    }
}

// ---------------------------------------------------------------------------
// Pass 2: per-row horizontal window via shared prefix scan, fused with
// log-softmax CE + weighted IoU terms; deterministic block reduction of the
// 4 accumulators into g_part[(b*H+y)*4 + k]. pred loads hoisted above the
// scan so their latency overlaps the scan dependency chain.
// Grid: (H, B), 512 threads (one pixel each).
__global__ void pass2_kernel(const float* __restrict__ pred) {
    const int y = blockIdx.x;
    const int b = blockIdx.y;
    const int x = threadIdx.x;
    const int lane = x & 31, warp = x >> 5;

    __shared__ float P[WW];
    __shared__ float wsum[16];
    __shared__ float red[16][4];

    const size_t rowbase = (size_t)b * HW + (size_t)y * WW;

    // Issue global loads first (independent of the scan chain).
    const float* pb = pred + ((size_t)b * 2) * HW + (size_t)y * WW + x;
    const float p0 = pb[0];
    const float p1 = pb[HW];
    const unsigned short cmv = g_cm[rowbase + x];

    // inclusive prefix scan of colsum row (exact: integer-valued <= 15872)
    float v = (float)(cmv & 255u);
    #pragma unroll
    for (int o = 1; o < 32; o <<= 1) {
        float n = __shfl_up_sync(0xffffffffu, v, o);
        if (lane >= o) v += n;
    }
    if (lane == 31) wsum[warp] = v;
    __syncthreads();
    if (warp == 0) {
        float t = (lane < 16) ? wsum[lane] : 0.f;
        #pragma unroll
        for (int o = 1; o < 16; o <<= 1) {
            float n = __shfl_up_sync(0xffffffffu, t, o);
            if (lane >= o) t += n;
        }
        if (lane < 16) wsum[lane] = t;
    }
    __syncthreads();
    float pref = v + ((warp > 0) ? wsum[warp - 1] : 0.f);
    P[x] = pref;
    __syncthreads();

    const int hi = (x + 15 < WW - 1) ? (x + 15) : (WW - 1);
    float win = P[hi] - ((x >= 16) ? P[x - 16] : 0.f);
    float pooled = win * (1.0f / 961.0f);

    float mf = (float)(cmv >> 8);

    float mx = fmaxf(p0, p1);
    float e0 = __expf(p0 - mx), e1 = __expf(p1 - mx);
    float lse = mx + __logf(e0 + e1);
    float logp0 = p0 - lse, logp1 = p1 - lse;

    float wbce = (mf > 0.5f) ? -logp1 : -logp0;
    float p1p  = __expf(logp1);
    float weit = 1.0f + 5.0f * fabsf(pooled - mf);

    float a0 = weit;                 // weit_sum
    float a1 = weit * wbce;          // weighted BCE
    float a2 = p1p * mf * weit;      // inter
    float a3 = (p1p + mf) * weit;    // cardinality

    // block reduce (deterministic)
    #pragma unroll
    for (int o = 16; o > 0; o >>= 1) {
        a0 += __shfl_down_sync(0xffffffffu, a0, o);
        a1 += __shfl_down_sync(0xffffffffu, a1, o);
        a2 += __shfl_down_sync(0xffffffffu, a2, o);
        a3 += __shfl_down_sync(0xffffffffu, a3, o);
    }
    if (lane == 0) { red[warp][0] = a0; red[warp][1] = a1; red[warp][2] = a2; red[warp][3] = a3; }
    __syncthreads();
    if (warp == 0) {
        float r0 = (lane < 16) ? red[lane][0] : 0.f;
        float r1 = (lane < 16) ? red[lane][1] : 0.f;
        float r2 = (lane < 16) ? red[lane][2] : 0.f;
        float r3 = (lane < 16) ? red[lane][3] : 0.f;
        #pragma unroll
        for (int o = 8; o > 0; o >>= 1) {
            r0 += __shfl_down_sync(0xffffffffu, r0, o);
            r1 += __shfl_down_sync(0xffffffffu, r1, o);
            r2 += __shfl_down_sync(0xffffffffu, r2, o);
            r3 += __shfl_down_sync(0xffffffffu, r3, o);
        }
        if (lane == 0) {
            float* out = g_part + ((size_t)b * HH + y) * 4;
            out[0] = r0; out[1] = r1; out[2] = r2; out[3] = r3;
        }
    }
}

// ---------------------------------------------------------------------------
// Pass 3: 16 blocks, block b reduces batch b's 512 row-partials (float4,
// coalesced), computes batch loss; last block (fenced atomic counter)
// averages the 16 losses, writes out[0], resets the counter (replay-safe).
__global__ void pass3_kernel(float* __restrict__ out) {
    const int b   = blockIdx.x;
    const int tid = threadIdx.x;          // 128 threads
    const int lane = tid & 31, warp = tid >> 5;

    const float4* p = (const float4*)g_part + (size_t)b * HH;
    float s0 = 0.f, s1 = 0.f, s2 = 0.f, s3 = 0.f;
    #pragma unroll
    for (int i = tid; i < HH; i += 128) {
        float4 v = p[i];
        s0 += v.x; s1 += v.y; s2 += v.z; s3 += v.w;
    }
    #pragma unroll
    for (int o = 16; o > 0; o >>= 1) {
        s0 += __shfl_down_sync(0xffffffffu, s0, o);
        s1 += __shfl_down_sync(0xffffffffu, s1, o);
        s2 += __shfl_down_sync(0xffffffffu, s2, o);
        s3 += __shfl_down_sync(0xffffffffu, s3, o);
    }
    __shared__ float red[4][4];
    if (lane == 0) { red[warp][0] = s0; red[warp][1] = s1; red[warp][2] = s2; red[warp][3] = s3; }
    __syncthreads();
    if (tid == 0) {
        float r0 = red[0][0] + red[1][0] + red[2][0] + red[3][0];
        float r1 = red[0][1] + red[1][1] + red[2][1] + red[3][1];
        float r2 = red[0][2] + red[1][2] + red[2][2] + red[3][2];
        float r3 = red[0][3] + red[1][3] + red[2][3] + red[3][3];

        float wbce  = r1 / r0;
        float inter = r2;
        float uni   = r3 - r2;                     // cardinality - inter
        float wiou  = 1.f - (inter + 1.f) / (uni + 1.f);
        g_lossb[b] = wbce + wiou;

        __threadfence();
        unsigned int old = atomicAdd(&g_count, 1u);
        if (old == (BB - 1)) {
            __threadfence();
            volatile float* lb = g_lossb;
            float t = 0.f;
            #pragma unroll
            for (int i = 0; i < BB; ++i) t += lb[i];
            out[0] = t * (1.f / (float)BB);
            atomicExch(&g_count, 0u);              // reset for next graph replay
        }
    }
}

// ---------------------------------------------------------------------------
extern "C" void kernel_launch(void* const* d_in, const int* in_sizes, int n_in,
                              void* d_out, int out_size) {
    const float* pred   = (const float*)d_in[0];
    const int*   mask32 = (const int*)d_in[1];   // 32-bit view; dtype detected in-kernel
    float* out = (float*)d_out;

    pass1_kernel<<<dim3(BB, 2, 16), 256>>>(mask32);
    pass2_kernel<<<dim3(HH, BB), 512>>>(pred);
    pass3_kernel<<<BB, 128>>>(out);
}

// round 5
// speedup vs baseline: 2.1754x; 1.6456x over previous
#include <cuda_runtime.h>
#include <cstdint>

#define BB 16
#define HH 512
#define WW 512
#define HW (HH*WW)
#define SEG 16            // output rows per pass1 block
#define TROWS (SEG + 30)  // 46 tile rows (15 halo each side)

// Scratch (no allocations allowed -> __device__ globals)
__device__ unsigned short g_cm  [BB*HW];      // packed (mask<<8)|colsum per pixel
__device__ float          g_part[BB*HH*4];    // per-(b,row) partial sums
__device__ float          g_lossb[BB];        // per-batch loss
__device__ unsigned int   g_count;            // completion counter (zero-init, self-reset)

// ---------------------------------------------------------------------------
// Pass 1 (v3): packed-byte SIMD vertical sliding 31-sum.
// Each thread owns 2 adjacent columns packed as bytes of a u16 (max byte
// value 62 -> packed add/sub is exact, no carries). Mask loaded with vector
// loads (int2 for int32, int4 for int64), tile staged in smem, output packed
// u16 = (mask<<8)|colsum written as one u32 per thread via byte_perm.
// Grid: (B, 32 y-segments of 16 rows), 256 threads (512 columns).
__global__ void pass1_kernel(const int* __restrict__ mask32) {
    const int tid = threadIdx.x;                 // 0..255 -> columns 2*tid, 2*tid+1
    const int b   = blockIdx.x;
    const int y0  = blockIdx.y * SEG;

    // --- dtype detection: int64 non-negative => all odd words are 0 ---
    __shared__ int sflag;
    if (tid == 0) sflag = 0;
    __syncthreads();
    {
        int v = mask32[2 * (tid & 63) + 1];
        if (v != 0) atomicOr(&sflag, 1);
    }
    __syncthreads();
    const bool is64 = (sflag == 0);

    __shared__ unsigned short tile[TROWS][256];

    if (is64) {
        const int* mb = mask32 + ((size_t)b * HW * 2);
        #pragma unroll 6
        for (int r = 0; r < TROWS; ++r) {
            const int y = y0 - 15 + r;
            unsigned u = 0;
            if (y >= 0 && y < HH) {
                int4 v = *(const int4*)(mb + (((size_t)y * WW + tid * 2) << 1));
                u = (unsigned)(v.x == 1) | ((unsigned)(v.z == 1) << 8);
            }
            tile[r][tid] = (unsigned short)u;
        }
    } else {
        const int* mb = mask32 + (size_t)b * HW;
        #pragma unroll 6
        for (int r = 0; r < TROWS; ++r) {
            const int y = y0 - 15 + r;
            unsigned u = 0;
            if (y >= 0 && y < HH) {
                int2 v = *(const int2*)(mb + ((size_t)y * WW + tid * 2));
                u = (unsigned)(v.x == 1) | ((unsigned)(v.y == 1) << 8);
            }
            tile[r][tid] = (unsigned short)u;
        }
    }
    __syncthreads();

    // packed warm-up sum over first 31 rows (bytes stay <= 31, no carry)
    unsigned sum = 0;
    #pragma unroll
    for (int r = 0; r < 31; ++r) sum += (unsigned)tile[r][tid];

    unsigned short* cm = g_cm + (size_t)b * HW;
    #pragma unroll
    for (int i = 0; i < SEG; ++i) {
        const int y = y0 + i;
        unsigned m = (unsigned)tile[15 + i][tid];
        // bytes [s0, m0, s1, m1] -> two little-endian u16: (m<<8)|s per column
        unsigned outw = __byte_perm(sum, m, 0x5140);
        *(unsigned*)(cm + (size_t)y * WW + tid * 2) = outw;
        if (i < SEG - 1)
            sum = sum + (unsigned)tile[31 + i][tid] - (unsigned)tile[i][tid];
    }
}

// ---------------------------------------------------------------------------
// Pass 2 (v3): one WARP per row, 16 pixels per thread, no __syncthreads.
// Thread-local integer prefix + warp scan; prefix stored in a 17-stride
// padded smem row (conflict-free for writes and both window reads).
// Log-softmax via single exp/log: d=p1-p0, a=|d|, l=log(1+exp(-a)):
//   wbce = l + (a if (d>=0) != (mask==1) else 0)
//   p1   = (d>=0 ? 1 : exp(-a)) / (1+exp(-a))
// Per-row accumulators warp-reduced and written to g_part.
// Grid: (32 row-groups, B), 512 threads = 16 warps = 16 rows.
__global__ void pass2_kernel(const float* __restrict__ pred) {
    const int lane = threadIdx.x & 31;
    const int w    = threadIdx.x >> 5;           // row within group
    const int y    = blockIdx.x * 16 + w;
    const int b    = blockIdx.y;

    __shared__ int sP[16][544];                  // padded prefix rows

    const size_t rowbase = (size_t)b * HW + (size_t)y * WW;

    // ---- issue all global loads up front (independent) ----
    const uint4* cmp = (const uint4*)(g_cm + rowbase) + lane * 2;
    uint4 c0 = cmp[0];
    uint4 c1 = cmp[1];

    const float4* q0p = (const float4*)(pred + ((size_t)(b * 2)     ) * HW + (size_t)y * WW) + lane * 4;
    const float4* q1p = (const float4*)(pred + ((size_t)(b * 2) + 1 ) * HW + (size_t)y * WW) + lane * 4;
    float4 q0[4], q1[4];
    #pragma unroll
    for (int i = 0; i < 4; ++i) { q0[i] = q0p[i]; q1[i] = q1p[i]; }

    // ---- unpack cm: colsum prefix + mask bits ----
    int pre[16];
    unsigned mb = 0;
    {
        int run = 0;
        const unsigned* cw0 = (const unsigned*)&c0;
        const unsigned* cw1 = (const unsigned*)&c1;
        #pragma unroll
        for (int j = 0; j < 16; ++j) {
            unsigned word = (j < 8) ? cw0[j >> 1] : cw1[(j - 8) >> 1];
            unsigned cmv  = (word >> ((j & 1) * 16)) & 0xffffu;
            run += (int)(cmv & 0xffu);
            pre[j] = run;
            mb |= ((cmv >> 8) & 1u) << j;
        }
    }

    // ---- warp scan of thread totals (exact integer) ----
    int tot = pre[15];
    int v = tot;
    #pragma unroll
    for (int o = 1; o < 32; o <<= 1) {
        int n = __shfl_up_sync(0xffffffffu, v, o);
        if (lane >= o) v += n;
    }
    const int base = v - tot;                    // exclusive prefix

    // ---- store padded prefix row:  idx(x) = x + (x>>4) = 17*lane + j ----
    #pragma unroll
    for (int j = 0; j < 16; ++j)
        sP[w][17 * lane + j] = base + pre[j];
    __syncwarp();

    // ---- per-pixel fused loss ----
    const float* f0 = (const float*)q0;
    const float* f1 = (const float*)q1;
    float a0 = 0.f, a1 = 0.f, a2 = 0.f, a3 = 0.f;
    #pragma unroll
    for (int j = 0; j < 16; ++j) {
        const int x  = lane * 16 + j;
        const int hi = (x + 15 < 511) ? (x + 15) : 511;
        int Ph = sP[w][hi + (hi >> 4)];
        int Pl = (x >= 16) ? sP[w][(x - 16) + ((x - 16) >> 4)] : 0;
        float pooled = (float)(Ph - Pl) * (1.0f / 961.0f);

        float mf = (float)((mb >> j) & 1u);

        float p0v = f0[j];
        float p1v = f1[j];
        float d = p1v - p0v;
        float a = fabsf(d);
        float e = __expf(-a);
        float l = __logf(1.0f + e);
        bool dpos = (d >= 0.f);
        bool m1   = ((mb >> j) & 1u) != 0u;

        float wbce = l + ((dpos == m1) ? 0.f : a);
        float p1prob = __fdividef(dpos ? 1.0f : e, 1.0f + e);
        float weit = 1.0f + 5.0f * fabsf(pooled - mf);

        a0 += weit;
        a1 += weit * wbce;
        a2 += p1prob * mf * weit;
        a3 += (p1prob + mf) * weit;
    }

    // ---- warp reduce & write row partials ----
    #pragma unroll
    for (int o = 16; o > 0; o >>= 1) {
        a0 += __shfl_down_sync(0xffffffffu, a0, o);
        a1 += __shfl_down_sync(0xffffffffu, a1, o);
        a2 += __shfl_down_sync(0xffffffffu, a2, o);
        a3 += __shfl_down_sync(0xffffffffu, a3, o);
    }
    if (lane == 0) {
        float* out = g_part + ((size_t)b * HH + y) * 4;
        out[0] = a0; out[1] = a1; out[2] = a2; out[3] = a3;
    }
}

// ---------------------------------------------------------------------------
// Pass 3: 16 blocks, block b reduces batch b's 512 row-partials (float4,
// coalesced), computes batch loss; last block (fenced atomic counter)
// averages the 16 losses, writes out[0], resets the counter (replay-safe).
__global__ void pass3_kernel(float* __restrict__ out) {
    const int b   = blockIdx.x;
    const int tid = threadIdx.x;          // 128 threads
    const int lane = tid & 31, warp = tid >> 5;

    const float4* p = (const float4*)g_part + (size_t)b * HH;
    float s0 = 0.f, s1 = 0.f, s2 = 0.f, s3 = 0.f;
    #pragma unroll
    for (int i = tid; i < HH; i += 128) {
        float4 v = p[i];
        s0 += v.x; s1 += v.y; s2 += v.z; s3 += v.w;
    }
    #pragma unroll
    for (int o = 16; o > 0; o >>= 1) {
        s0 += __shfl_down_sync(0xffffffffu, s0, o);
        s1 += __shfl_down_sync(0xffffffffu, s1, o);
        s2 += __shfl_down_sync(0xffffffffu, s2, o);
        s3 += __shfl_down_sync(0xffffffffu, s3, o);
    }
    __shared__ float red[4][4];
    if (lane == 0) { red[warp][0] = s0; red[warp][1] = s1; red[warp][2] = s2; red[warp][3] = s3; }
    __syncthreads();
    if (tid == 0) {
        float r0 = red[0][0] + red[1][0] + red[2][0] + red[3][0];
        float r1 = red[0][1] + red[1][1] + red[2][1] + red[3][1];
        float r2 = red[0][2] + red[1][2] + red[2][2] + red[3][2];
        float r3 = red[0][3] + red[1][3] + red[2][3] + red[3][3];

        float wbce  = r1 / r0;
        float inter = r2;
        float uni   = r3 - r2;                     // cardinality - inter
        float wiou  = 1.f - (inter + 1.f) / (uni + 1.f);
        g_lossb[b] = wbce + wiou;

        __threadfence();
        unsigned int old = atomicAdd(&g_count, 1u);
        if (old == (BB - 1)) {
            __threadfence();
            volatile float* lb = g_lossb;
            float t = 0.f;
            #pragma unroll
            for (int i = 0; i < BB; ++i) t += lb[i];
            out[0] = t * (1.f / (float)BB);
            atomicExch(&g_count, 0u);              // reset for next graph replay
        }
    }
}

// ---------------------------------------------------------------------------
extern "C" void kernel_launch(void* const* d_in, const int* in_sizes, int n_in,
                              void* d_out, int out_size) {
    const float* pred   = (const float*)d_in[0];
    const int*   mask32 = (const int*)d_in[1];   // 32-bit view; dtype detected in-kernel
    float* out = (float*)d_out;

    pass1_kernel<<<dim3(BB, 32), 256>>>(mask32);
    pass2_kernel<<<dim3(32, BB), 512>>>(pred);
    pass3_kernel<<<BB, 128>>>(out);
}